// round 8
// baseline (speedup 1.0000x reference)
#include <cuda_runtime.h>
#include <cuda_fp16.h>

#define HID 128
#define NMAX 20000
#define EMAX 640000

// ---- scratch (__device__ globals; allocation-free rule) ----
__device__ int    g_is64;
__device__ int    g_cnt[NMAX];            // dense histogram
__device__ int    g_rank[EMAX];           // per-edge within-node rank
__device__ int    g_prefix[NMAX + 1];
__device__ int    g_srcs[EMAX];
__device__ __half g_feat16[NMAX * HID];   // fp16 copy of features
__device__ float  g_agg[NMAX * HID];      // mean-aggregated features

// ---------------------------------------------------------------------------
// Kernel 1a: zero counters + probe edge dtype (fast; heads the edge chain).
// ---------------------------------------------------------------------------
__global__ void __launch_bounds__(256) zero_detect_kernel(
    const unsigned* __restrict__ w, int m, int n)
{
    int i = blockIdx.x * blockDim.x + threadIdx.x;
    if (i < n) g_cnt[i] = 0;
    if (i == 0) g_is64 = 1;
    if (blockIdx.x == 0) {
        int bad = 0;
        for (int j = threadIdx.x; j < m; j += blockDim.x)
            if (w[2 * j + 1] != 0u) bad = 1;
        if (__syncthreads_or(bad) && threadIdx.x == 0) g_is64 = 0;
    }
}

// ---------------------------------------------------------------------------
// Kernel 1b: feat -> fp16 (independent; runs on side stream).
// ---------------------------------------------------------------------------
__global__ void __launch_bounds__(256) tofp16_kernel(
    const float* __restrict__ feat, int n)
{
    int k = blockIdx.x * blockDim.x + threadIdx.x;
    int tot4 = n * HID / 4;
    if (k >= tot4) return;
    float4 v = ((const float4*)feat)[k];
    __half2 h0 = __floats2half2_rn(v.x, v.y);
    __half2 h1 = __floats2half2_rn(v.z, v.w);
    uint2 o;
    o.x = *(unsigned*)&h0;
    o.y = *(unsigned*)&h1;
    ((uint2*)g_feat16)[k] = o;
}

// ---------------------------------------------------------------------------
// Kernel 2: histogram WITH rank capture. 2 edges/thread (occupancy + MLP).
// ---------------------------------------------------------------------------
__global__ void __launch_bounds__(256) hist_rank_kernel(const void* __restrict__ ei, int E) {
    int base = (blockIdx.x * blockDim.x + threadIdx.x) * 2;
    if (base >= E) return;
    int m = min(2, E - base);
    int d[2];
    if (g_is64) {
        const long long* p = (const long long*)ei + E;
#pragma unroll
        for (int i = 0; i < 2; i++) if (i < m) d[i] = (int)p[base + i];
    } else {
        const int* p = (const int*)ei + E;
#pragma unroll
        for (int i = 0; i < 2; i++) if (i < m) d[i] = p[base + i];
    }
    int r[2];
#pragma unroll
    for (int i = 0; i < 2; i++) if (i < m) r[i] = atomicAdd(&g_cnt[d[i]], 1);
#pragma unroll
    for (int i = 0; i < 2; i++) if (i < m) g_rank[base + i] = r[i];
}

// ---------------------------------------------------------------------------
// Kernel 3: single-block exclusive scan (dense contiguous reads).
// ---------------------------------------------------------------------------
__global__ void __launch_bounds__(1024) scan_kernel(int n) {
    __shared__ int warp_sums[32];
    int t = threadIdx.x;
    int lane = t & 31, wid = t >> 5;
    int chunk = (n + 1023) / 1024;
    int beg = t * chunk;
    int end = min(beg + chunk, n);

    int s = 0;
    for (int i = beg; i < end; i++) s += g_cnt[i];

    int v = s;
#pragma unroll
    for (int o = 1; o < 32; o <<= 1) {
        int u = __shfl_up_sync(0xffffffffu, v, o);
        if (lane >= o) v += u;
    }
    if (lane == 31) warp_sums[wid] = v;
    __syncthreads();
    if (wid == 0) {
        int w = warp_sums[lane];
#pragma unroll
        for (int o = 1; o < 32; o <<= 1) {
            int u = __shfl_up_sync(0xffffffffu, w, o);
            if (lane >= o) w += u;
        }
        warp_sums[lane] = w;
    }
    __syncthreads();

    int run = v - s + (wid > 0 ? warp_sums[wid - 1] : 0);
    for (int i = beg; i < end; i++) {
        int c = g_cnt[i];
        g_prefix[i] = run;
        run += c;
    }
    if (t == 0) g_prefix[n] = warp_sums[31];
}

// ---------------------------------------------------------------------------
// Kernel 4: atomic-free placement: srcs[prefix[dst] + rank[e]] = src.
// 2 edges/thread -> 1250 blocks (occupancy).
// ---------------------------------------------------------------------------
__global__ void __launch_bounds__(256) place_kernel(const void* __restrict__ ei, int E) {
    int base = (blockIdx.x * blockDim.x + threadIdx.x) * 2;
    if (base >= E) return;
    int m = min(2, E - base);
    int s[2], d[2], r[2];
    if (g_is64) {
        const long long* p = (const long long*)ei;
#pragma unroll
        for (int i = 0; i < 2; i++) if (i < m) { s[i] = (int)p[base + i]; d[i] = (int)p[E + base + i]; }
    } else {
        const int* p = (const int*)ei;
#pragma unroll
        for (int i = 0; i < 2; i++) if (i < m) { s[i] = p[base + i]; d[i] = p[E + base + i]; }
    }
#pragma unroll
    for (int i = 0; i < 2; i++) if (i < m) r[i] = g_rank[base + i];
    int pf[2];
#pragma unroll
    for (int i = 0; i < 2; i++) if (i < m) pf[i] = g_prefix[d[i]];
#pragma unroll
    for (int i = 0; i < 2; i++) if (i < m) g_srcs[pf[i] + r[i]] = s[i];
}

// ---------------------------------------------------------------------------
// One warp per dst node: gather-sum fp16 src features (4-deep MLP),
// fp32 accumulate, write fp32 mean.
// ---------------------------------------------------------------------------
__global__ void __launch_bounds__(256) agg_kernel(int n) {
    int node = (blockIdx.x * blockDim.x + threadIdx.x) >> 5;
    int lane = threadIdx.x & 31;
    if (node >= n) return;
    int beg = g_prefix[node], end = g_prefix[node + 1];

    const uint2* f16 = (const uint2*)g_feat16;

    float4 a0 = make_float4(0.f, 0.f, 0.f, 0.f);
    float4 a1 = a0, a2 = a0, a3 = a0;

    auto addv = [](float4& a, uint2 v) {
        __half2 h0 = *(__half2*)&v.x;
        __half2 h1 = *(__half2*)&v.y;
        float2 f0 = __half22float2(h0);
        float2 f1 = __half22float2(h1);
        a.x += f0.x; a.y += f0.y; a.z += f1.x; a.w += f1.y;
    };

    int e = beg;
    for (; e + 4 <= end; e += 4) {
        int s0 = g_srcs[e + 0], s1 = g_srcs[e + 1];
        int s2 = g_srcs[e + 2], s3 = g_srcs[e + 3];
        uint2 v0 = f16[(size_t)s0 * 32 + lane];
        uint2 v1 = f16[(size_t)s1 * 32 + lane];
        uint2 v2 = f16[(size_t)s2 * 32 + lane];
        uint2 v3 = f16[(size_t)s3 * 32 + lane];
        addv(a0, v0); addv(a1, v1); addv(a2, v2); addv(a3, v3);
    }
    for (; e < end; e++) {
        uint2 v = f16[(size_t)g_srcs[e] * 32 + lane];
        addv(a0, v);
    }
    float inv = (end > beg) ? 1.f / (float)(end - beg) : 0.f;
    float4 s;
    s.x = (a0.x + a1.x + a2.x + a3.x) * inv;
    s.y = (a0.y + a1.y + a2.y + a3.y) * inv;
    s.z = (a0.z + a1.z + a2.z + a3.z) * inv;
    s.w = (a0.w + a1.w + a2.w + a3.w) * inv;
    *(float4*)(g_agg + (size_t)node * HID + lane * 4) = s;
}

// ---------------------------------------------------------------------------
// TF32 tensor-core GEMM: out = agg @ Wl^T + feat @ Wr^T + bl
// ---------------------------------------------------------------------------
#define BM 128
#define BK 16
#define SW(r, c) ((r) * BK + ((c) ^ ((((r) >> 1) & 3) << 2)))

__device__ __forceinline__ unsigned f2tf32(float x) {
    unsigned r;
    asm("cvt.rna.tf32.f32 %0, %1;" : "=r"(r) : "f"(x));
    return r;
}

__device__ __forceinline__ void mma_tf32(float* c, const unsigned* a, const unsigned* b) {
    asm volatile(
        "mma.sync.aligned.m16n8k8.row.col.f32.tf32.tf32.f32 "
        "{%0,%1,%2,%3},{%4,%5,%6,%7},{%8,%9},{%0,%1,%2,%3};"
        : "+f"(c[0]), "+f"(c[1]), "+f"(c[2]), "+f"(c[3])
        : "r"(a[0]), "r"(a[1]), "r"(a[2]), "r"(a[3]), "r"(b[0]), "r"(b[1]));
}

__global__ void __launch_bounds__(256) gemm_tc(
    const float* __restrict__ feat,
    const float* __restrict__ Wl,
    const float* __restrict__ bl,
    const float* __restrict__ Wr,
    float* __restrict__ out,
    int n)
{
    __shared__ unsigned sA[2][BM * BK];
    __shared__ unsigned sB[2][128 * BK];

    int tid = threadIdx.x;
    int wid = tid >> 5, lane = tid & 31;
    int wm = wid & 1;
    int wn = wid >> 1;
    int g = lane >> 2;
    int tg = lane & 3;
    int row0 = blockIdx.x * BM;

    float acc[4][4][4];
#pragma unroll
    for (int mt = 0; mt < 4; mt++)
#pragma unroll
        for (int nt = 0; nt < 4; nt++)
#pragma unroll
            for (int q = 0; q < 4; q++) acc[mt][nt][q] = 0.f;

    uint4 rga[2], rgb[2];

    auto ldg_chunk = [&](int ck) {
        const float* A = (ck < 8) ? g_agg : feat;
        const float* W = (ck < 8) ? Wl : Wr;
        int k0 = (ck & 7) * BK;
#pragma unroll
        for (int q = 0; q < 2; q++) {
            int idx = q * 256 + tid;
            int r = idx >> 2;
            int c4 = (idx & 3) * 4;
            int gr = row0 + r;
            float4 v = make_float4(0.f, 0.f, 0.f, 0.f);
            if (gr < n) v = *(const float4*)(A + (size_t)gr * HID + k0 + c4);
            rga[q] = make_uint4(f2tf32(v.x), f2tf32(v.y), f2tf32(v.z), f2tf32(v.w));
            float4 w = *(const float4*)(W + (size_t)r * HID + k0 + c4);
            rgb[q] = make_uint4(f2tf32(w.x), f2tf32(w.y), f2tf32(w.z), f2tf32(w.w));
        }
    };

    auto sts_chunk = [&](int b) {
#pragma unroll
        for (int q = 0; q < 2; q++) {
            int idx = q * 256 + tid;
            int r = idx >> 2;
            int c4 = (idx & 3) * 4;
            *(uint4*)&sA[b][SW(r, c4)] = rga[q];
            *(uint4*)&sB[b][SW(r, c4)] = rgb[q];
        }
    };

    ldg_chunk(0);
    sts_chunk(0);
    __syncthreads();

    for (int ck = 0; ck < 16; ck++) {
        if (ck < 15) ldg_chunk(ck + 1);
        int b = ck & 1;
#pragma unroll
        for (int kk = 0; kk < 2; kk++) {
            int ko = kk * 8;
            unsigned af[4][4], bf[4][2];
#pragma unroll
            for (int mt = 0; mt < 4; mt++) {
                int rb_ = wm * 64 + mt * 16;
                af[mt][0] = sA[b][SW(rb_ + g,     ko + tg)];
                af[mt][1] = sA[b][SW(rb_ + g + 8, ko + tg)];
                af[mt][2] = sA[b][SW(rb_ + g,     ko + tg + 4)];
                af[mt][3] = sA[b][SW(rb_ + g + 8, ko + tg + 4)];
            }
#pragma unroll
            for (int nt = 0; nt < 4; nt++) {
                int cb = wn * 32 + nt * 8;
                bf[nt][0] = sB[b][SW(cb + g, ko + tg)];
                bf[nt][1] = sB[b][SW(cb + g, ko + tg + 4)];
            }
#pragma unroll
            for (int mt = 0; mt < 4; mt++)
#pragma unroll
                for (int nt = 0; nt < 4; nt++)
                    mma_tf32(acc[mt][nt], af[mt], bf[nt]);
        }
        if (ck < 15) {
            sts_chunk((ck + 1) & 1);
            __syncthreads();
        }
    }

#pragma unroll
    for (int nt = 0; nt < 4; nt++) {
        int c = wn * 32 + nt * 8 + tg * 2;
        float b0 = bl[c], b1 = bl[c + 1];
#pragma unroll
        for (int mt = 0; mt < 4; mt++) {
            int r = row0 + wm * 64 + mt * 16 + g;
            if (r < n) {
                float2 o = make_float2(acc[mt][nt][0] + b0, acc[mt][nt][1] + b1);
                *(float2*)(out + (size_t)r * HID + c) = o;
            }
            if (r + 8 < n) {
                float2 o = make_float2(acc[mt][nt][2] + b0, acc[mt][nt][3] + b1);
                *(float2*)(out + (size_t)(r + 8) * HID + c) = o;
            }
        }
    }
}

// ---------------------------------------------------------------------------
// Side stream + events for fork/join inside graph capture. Created once at
// static-init time (no device-memory delta at harness checkpoints).
// ---------------------------------------------------------------------------
static cudaStream_t g_s2;
static cudaEvent_t  g_evF, g_evJ;
static bool         g_fork_ok = false;

namespace {
struct CtorInit {
    CtorInit() {
        g_fork_ok =
            cudaStreamCreateWithFlags(&g_s2, cudaStreamNonBlocking) == cudaSuccess &&
            cudaEventCreateWithFlags(&g_evF, cudaEventDisableTiming) == cudaSuccess &&
            cudaEventCreateWithFlags(&g_evJ, cudaEventDisableTiming) == cudaSuccess;
    }
};
CtorInit g_ctor;
}

// ---------------------------------------------------------------------------
extern "C" void kernel_launch(void* const* d_in, const int* in_sizes, int n_in,
                              void* d_out, int out_size)
{
    const float* feat = (const float*)d_in[0];
    const void*  ei   = d_in[1];
    const float* Wl   = (const float*)d_in[2];
    const float* bl   = (const float*)d_in[3];
    const float* Wr   = (const float*)d_in[4];
    float* out = (float*)d_out;

    int n = in_sizes[0] / HID;          // 20000
    int E = in_sizes[1] / 2;            // 640000

    int n_check = E < 4096 ? E : 4096;
    int conv_blocks = (n * HID / 4 + 255) / 256;
    int eb2 = (E / 2 + 255) / 256;

    if (g_fork_ok) {
        // fork: fp16 conversion runs concurrently with the edge chain
        cudaEventRecord(g_evF, 0);
        cudaStreamWaitEvent(g_s2, g_evF, 0);
        tofp16_kernel<<<conv_blocks, 256, 0, g_s2>>>(feat, n);
        cudaEventRecord(g_evJ, g_s2);
    } else {
        tofp16_kernel<<<conv_blocks, 256>>>(feat, n);
    }

    zero_detect_kernel<<<(n + 255) / 256, 256>>>((const unsigned*)ei, n_check, n);
    hist_rank_kernel<<<eb2, 256>>>(ei, E);
    scan_kernel<<<1, 1024>>>(n);
    place_kernel<<<eb2, 256>>>(ei, E);

    if (g_fork_ok) cudaStreamWaitEvent(0, g_evJ, 0);   // join before agg

    agg_kernel<<<(n * 32 + 255) / 256, 256>>>(n);
    gemm_tc<<<(n + BM - 1) / BM, 256>>>(feat, Wl, bl, Wr, out, n);
}

// round 9
// speedup vs baseline: 1.1366x; 1.1366x over previous
#include <cuda_runtime.h>
#include <cuda_fp16.h>

#define HID 128
#define NMAX 20000
#define EMAX 640000

// ---- scratch (__device__ globals; allocation-free rule) ----
__device__ int    g_is64;
__device__ __align__(16) int g_cnt[NMAX];          // dense histogram
__device__ __align__(16) int g_prefix[NMAX + 4];   // CSR offsets (+pad)
__device__ int    g_rank[EMAX];                    // per-edge within-node rank
__device__ int    g_srcs[EMAX];
__device__ __half g_feat16[NMAX * HID];            // fp16 copy of features
__device__ float  g_agg[NMAX * HID];               // mean-aggregated features

// ---------------------------------------------------------------------------
// Kernel 1: zero counters, probe edge dtype, convert feat -> fp16.
// ---------------------------------------------------------------------------
__global__ void __launch_bounds__(256) init_kernel(
    const unsigned* __restrict__ w, int m,
    const float* __restrict__ feat, int n)
{
    int i = blockIdx.x * blockDim.x + threadIdx.x;
    int stride = gridDim.x * blockDim.x;
    if (i < n) g_cnt[i] = 0;
    if (i == 0) g_is64 = 1;
    if (blockIdx.x == 0) {
        int bad = 0;
        for (int j = threadIdx.x; j < m; j += blockDim.x)
            if (w[2 * j + 1] != 0u) bad = 1;
        if (__syncthreads_or(bad) && threadIdx.x == 0) g_is64 = 0;
    }
    int tot4 = n * HID / 4;
    const float4* f4 = (const float4*)feat;
    uint2* h4 = (uint2*)g_feat16;
    for (int k = i; k < tot4; k += stride) {
        float4 v = f4[k];
        __half2 h0 = __floats2half2_rn(v.x, v.y);
        __half2 h1 = __floats2half2_rn(v.z, v.w);
        uint2 o;
        o.x = *(unsigned*)&h0;
        o.y = *(unsigned*)&h1;
        h4[k] = o;
    }
}

// ---------------------------------------------------------------------------
// Kernel 2: histogram WITH rank capture. 2 edges/thread (occupancy + MLP).
// ---------------------------------------------------------------------------
__global__ void __launch_bounds__(256) hist_rank_kernel(const void* __restrict__ ei, int E) {
    int base = (blockIdx.x * blockDim.x + threadIdx.x) * 2;
    if (base >= E) return;
    int m = min(2, E - base);
    int d[2];
    if (g_is64) {
        const long long* p = (const long long*)ei + E;
#pragma unroll
        for (int i = 0; i < 2; i++) if (i < m) d[i] = (int)p[base + i];
    } else {
        const int* p = (const int*)ei + E;
#pragma unroll
        for (int i = 0; i < 2; i++) if (i < m) d[i] = p[base + i];
    }
    int r[2];
#pragma unroll
    for (int i = 0; i < 2; i++) if (i < m) r[i] = atomicAdd(&g_cnt[d[i]], 1);
#pragma unroll
    for (int i = 0; i < 2; i++) if (i < m) g_rank[base + i] = r[i];
}

// ---------------------------------------------------------------------------
// Kernel 3: single-block scan, register-cached & int4-vectorized.
// Each thread: 5x int4 independent loads -> 20 counts in registers ->
// shuffle scan of thread sums -> 5x int4 prefix stores. No re-reads.
// ---------------------------------------------------------------------------
#define SCH 20   // counts per thread (1024 threads cover 20480)

__global__ void __launch_bounds__(1024) scan_kernel(int n) {
    __shared__ int warp_sums[32];
    int t = threadIdx.x;
    int lane = t & 31, wid = t >> 5;
    int beg = t * SCH;

    int c[SCH];
    int s = 0;
    bool full = (beg + SCH <= n);
    if (full) {
        const int4* p = (const int4*)(g_cnt + beg);
#pragma unroll
        for (int q = 0; q < SCH / 4; q++) {
            int4 v = p[q];
            c[q * 4 + 0] = v.x; c[q * 4 + 1] = v.y;
            c[q * 4 + 2] = v.z; c[q * 4 + 3] = v.w;
            s += v.x + v.y + v.z + v.w;
        }
    } else {
#pragma unroll
        for (int q = 0; q < SCH; q++) {
            int idx = beg + q;
            c[q] = (idx < n) ? g_cnt[idx] : 0;
            s += c[q];
        }
    }

    // two-level shuffle scan of per-thread sums
    int v = s;
#pragma unroll
    for (int o = 1; o < 32; o <<= 1) {
        int u = __shfl_up_sync(0xffffffffu, v, o);
        if (lane >= o) v += u;
    }
    if (lane == 31) warp_sums[wid] = v;
    __syncthreads();
    if (wid == 0) {
        int w = warp_sums[lane];
#pragma unroll
        for (int o = 1; o < 32; o <<= 1) {
            int u = __shfl_up_sync(0xffffffffu, w, o);
            if (lane >= o) w += u;
        }
        warp_sums[lane] = w;
    }
    __syncthreads();

    int run = v - s + (wid > 0 ? warp_sums[wid - 1] : 0);  // exclusive prefix
    int pre[SCH];
#pragma unroll
    for (int q = 0; q < SCH; q++) { pre[q] = run; run += c[q]; }

    if (full) {
        int4* p = (int4*)(g_prefix + beg);
#pragma unroll
        for (int q = 0; q < SCH / 4; q++)
            p[q] = make_int4(pre[q * 4 + 0], pre[q * 4 + 1],
                             pre[q * 4 + 2], pre[q * 4 + 3]);
    } else {
#pragma unroll
        for (int q = 0; q < SCH; q++)
            if (beg + q < n) g_prefix[beg + q] = pre[q];
    }
    if (t == 0) g_prefix[n] = warp_sums[31];
}

// ---------------------------------------------------------------------------
// Kernel 4: atomic-free placement: srcs[prefix[dst] + rank[e]] = src.
// ---------------------------------------------------------------------------
__global__ void __launch_bounds__(256) place_kernel(const void* __restrict__ ei, int E) {
    int base = (blockIdx.x * blockDim.x + threadIdx.x) * 2;
    if (base >= E) return;
    int m = min(2, E - base);
    int s[2], d[2], r[2];
    if (g_is64) {
        const long long* p = (const long long*)ei;
#pragma unroll
        for (int i = 0; i < 2; i++) if (i < m) { s[i] = (int)p[base + i]; d[i] = (int)p[E + base + i]; }
    } else {
        const int* p = (const int*)ei;
#pragma unroll
        for (int i = 0; i < 2; i++) if (i < m) { s[i] = p[base + i]; d[i] = p[E + base + i]; }
    }
#pragma unroll
    for (int i = 0; i < 2; i++) if (i < m) r[i] = g_rank[base + i];
    int pf[2];
#pragma unroll
    for (int i = 0; i < 2; i++) if (i < m) pf[i] = g_prefix[d[i]];
#pragma unroll
    for (int i = 0; i < 2; i++) if (i < m) g_srcs[pf[i] + r[i]] = s[i];
}

// ---------------------------------------------------------------------------
// One warp per dst node: gather-sum fp16 src features (4-deep MLP),
// fp32 accumulate, write fp32 mean.
// ---------------------------------------------------------------------------
__global__ void __launch_bounds__(256) agg_kernel(int n) {
    int node = (blockIdx.x * blockDim.x + threadIdx.x) >> 5;
    int lane = threadIdx.x & 31;
    if (node >= n) return;
    int beg = g_prefix[node], end = g_prefix[node + 1];

    const uint2* f16 = (const uint2*)g_feat16;

    float4 a0 = make_float4(0.f, 0.f, 0.f, 0.f);
    float4 a1 = a0, a2 = a0, a3 = a0;

    auto addv = [](float4& a, uint2 v) {
        __half2 h0 = *(__half2*)&v.x;
        __half2 h1 = *(__half2*)&v.y;
        float2 f0 = __half22float2(h0);
        float2 f1 = __half22float2(h1);
        a.x += f0.x; a.y += f0.y; a.z += f1.x; a.w += f1.y;
    };

    int e = beg;
    for (; e + 4 <= end; e += 4) {
        int s0 = g_srcs[e + 0], s1 = g_srcs[e + 1];
        int s2 = g_srcs[e + 2], s3 = g_srcs[e + 3];
        uint2 v0 = f16[(size_t)s0 * 32 + lane];
        uint2 v1 = f16[(size_t)s1 * 32 + lane];
        uint2 v2 = f16[(size_t)s2 * 32 + lane];
        uint2 v3 = f16[(size_t)s3 * 32 + lane];
        addv(a0, v0); addv(a1, v1); addv(a2, v2); addv(a3, v3);
    }
    for (; e < end; e++) {
        uint2 v = f16[(size_t)g_srcs[e] * 32 + lane];
        addv(a0, v);
    }
    float inv = (end > beg) ? 1.f / (float)(end - beg) : 0.f;
    float4 s;
    s.x = (a0.x + a1.x + a2.x + a3.x) * inv;
    s.y = (a0.y + a1.y + a2.y + a3.y) * inv;
    s.z = (a0.z + a1.z + a2.z + a3.z) * inv;
    s.w = (a0.w + a1.w + a2.w + a3.w) * inv;
    *(float4*)(g_agg + (size_t)node * HID + lane * 4) = s;
}

// ---------------------------------------------------------------------------
// TF32 tensor-core GEMM: out = agg @ Wl^T + feat @ Wr^T + bl
// ---------------------------------------------------------------------------
#define BM 128
#define BK 16
#define SW(r, c) ((r) * BK + ((c) ^ ((((r) >> 1) & 3) << 2)))

__device__ __forceinline__ unsigned f2tf32(float x) {
    unsigned r;
    asm("cvt.rna.tf32.f32 %0, %1;" : "=r"(r) : "f"(x));
    return r;
}

__device__ __forceinline__ void mma_tf32(float* c, const unsigned* a, const unsigned* b) {
    asm volatile(
        "mma.sync.aligned.m16n8k8.row.col.f32.tf32.tf32.f32 "
        "{%0,%1,%2,%3},{%4,%5,%6,%7},{%8,%9},{%0,%1,%2,%3};"
        : "+f"(c[0]), "+f"(c[1]), "+f"(c[2]), "+f"(c[3])
        : "r"(a[0]), "r"(a[1]), "r"(a[2]), "r"(a[3]), "r"(b[0]), "r"(b[1]));
}

__global__ void __launch_bounds__(256) gemm_tc(
    const float* __restrict__ feat,
    const float* __restrict__ Wl,
    const float* __restrict__ bl,
    const float* __restrict__ Wr,
    float* __restrict__ out,
    int n)
{
    __shared__ unsigned sA[2][BM * BK];
    __shared__ unsigned sB[2][128 * BK];

    int tid = threadIdx.x;
    int wid = tid >> 5, lane = tid & 31;
    int wm = wid & 1;
    int wn = wid >> 1;
    int g = lane >> 2;
    int tg = lane & 3;
    int row0 = blockIdx.x * BM;

    float acc[4][4][4];
#pragma unroll
    for (int mt = 0; mt < 4; mt++)
#pragma unroll
        for (int nt = 0; nt < 4; nt++)
#pragma unroll
            for (int q = 0; q < 4; q++) acc[mt][nt][q] = 0.f;

    uint4 rga[2], rgb[2];

    auto ldg_chunk = [&](int ck) {
        const float* A = (ck < 8) ? g_agg : feat;
        const float* W = (ck < 8) ? Wl : Wr;
        int k0 = (ck & 7) * BK;
#pragma unroll
        for (int q = 0; q < 2; q++) {
            int idx = q * 256 + tid;
            int r = idx >> 2;
            int c4 = (idx & 3) * 4;
            int gr = row0 + r;
            float4 v = make_float4(0.f, 0.f, 0.f, 0.f);
            if (gr < n) v = *(const float4*)(A + (size_t)gr * HID + k0 + c4);
            rga[q] = make_uint4(f2tf32(v.x), f2tf32(v.y), f2tf32(v.z), f2tf32(v.w));
            float4 w = *(const float4*)(W + (size_t)r * HID + k0 + c4);
            rgb[q] = make_uint4(f2tf32(w.x), f2tf32(w.y), f2tf32(w.z), f2tf32(w.w));
        }
    };

    auto sts_chunk = [&](int b) {
#pragma unroll
        for (int q = 0; q < 2; q++) {
            int idx = q * 256 + tid;
            int r = idx >> 2;
            int c4 = (idx & 3) * 4;
            *(uint4*)&sA[b][SW(r, c4)] = rga[q];
            *(uint4*)&sB[b][SW(r, c4)] = rgb[q];
        }
    };

    ldg_chunk(0);
    sts_chunk(0);
    __syncthreads();

    for (int ck = 0; ck < 16; ck++) {
        if (ck < 15) ldg_chunk(ck + 1);
        int b = ck & 1;
#pragma unroll
        for (int kk = 0; kk < 2; kk++) {
            int ko = kk * 8;
            unsigned af[4][4], bf[4][2];
#pragma unroll
            for (int mt = 0; mt < 4; mt++) {
                int rb_ = wm * 64 + mt * 16;
                af[mt][0] = sA[b][SW(rb_ + g,     ko + tg)];
                af[mt][1] = sA[b][SW(rb_ + g + 8, ko + tg)];
                af[mt][2] = sA[b][SW(rb_ + g,     ko + tg + 4)];
                af[mt][3] = sA[b][SW(rb_ + g + 8, ko + tg + 4)];
            }
#pragma unroll
            for (int nt = 0; nt < 4; nt++) {
                int cb = wn * 32 + nt * 8;
                bf[nt][0] = sB[b][SW(cb + g, ko + tg)];
                bf[nt][1] = sB[b][SW(cb + g, ko + tg + 4)];
            }
#pragma unroll
            for (int mt = 0; mt < 4; mt++)
#pragma unroll
                for (int nt = 0; nt < 4; nt++)
                    mma_tf32(acc[mt][nt], af[mt], bf[nt]);
        }
        if (ck < 15) {
            sts_chunk((ck + 1) & 1);
            __syncthreads();
        }
    }

#pragma unroll
    for (int nt = 0; nt < 4; nt++) {
        int c = wn * 32 + nt * 8 + tg * 2;
        float b0 = bl[c], b1 = bl[c + 1];
#pragma unroll
        for (int mt = 0; mt < 4; mt++) {
            int r = row0 + wm * 64 + mt * 16 + g;
            if (r < n) {
                float2 o = make_float2(acc[mt][nt][0] + b0, acc[mt][nt][1] + b1);
                *(float2*)(out + (size_t)r * HID + c) = o;
            }
            if (r + 8 < n) {
                float2 o = make_float2(acc[mt][nt][2] + b0, acc[mt][nt][3] + b1);
                *(float2*)(out + (size_t)(r + 8) * HID + c) = o;
            }
        }
    }
}

// ---------------------------------------------------------------------------
extern "C" void kernel_launch(void* const* d_in, const int* in_sizes, int n_in,
                              void* d_out, int out_size)
{
    const float* feat = (const float*)d_in[0];
    const void*  ei   = d_in[1];
    const float* Wl   = (const float*)d_in[2];
    const float* bl   = (const float*)d_in[3];
    const float* Wr   = (const float*)d_in[4];
    float* out = (float*)d_out;

    int n = in_sizes[0] / HID;          // 20000
    int E = in_sizes[1] / 2;            // 640000

    int n_check = E < 4096 ? E : 4096;
    init_kernel<<<1184, 256>>>((const unsigned*)ei, n_check, feat, n);

    int eb2 = (E / 2 + 255) / 256;
    hist_rank_kernel<<<eb2, 256>>>(ei, E);
    scan_kernel<<<1, 1024>>>(n);
    place_kernel<<<eb2, 256>>>(ei, E);

    agg_kernel<<<(n * 32 + 255) / 256, 256>>>(n);

    gemm_tc<<<(n + BM - 1) / BM, 256>>>(feat, Wl, bl, Wr, out, n);
}